// round 3
// baseline (speedup 1.0000x reference)
#include <cuda_runtime.h>

// Problem constants
#define Tn 336
#define Fn 12
#define Hn 50
#define Bn 4096
#define BC 32          // batch rows per CTA
#define NTHREADS 256
#define HPAD 52        // h row stride (float4-aligned)

// shared memory float offsets
#define W0_OFF 0                 // layer0 combined [62][50][4]  = 12400 floats
#define W1_OFF 12400             // layer1 combined [100][50][4] = 20000
#define W2_OFF 32400             // layer2 combined [100][50][4] = 20000
#define HS_OFF 52400             // h state  3 * 32 * 52 = 4992
#define XS_OFF 57392             // x tile   32 * 12 = 384
#define SMEM_FLOATS 57776
#define SMEM_BYTES (SMEM_FLOATS * 4)

__device__ __forceinline__ void fma4(float4& z, const float4 wv, const float s) {
    z.x += wv.x * s;
    z.y += wv.y * s;
    z.z += wv.z * s;
    z.w += wv.w * s;
}

__device__ __forceinline__ float sigmoidf_(float v) {
    return 1.0f / (1.0f + __expf(-v));
}

// Accumulate z[r] += sum_{j<50} W[j][u][gate] * h[r][j]
// Wb layout: element (j,u,g) at Wb[(j*50+u)*4+g]; hb: row base, stride HPAD.
__device__ __forceinline__ void acc50(float4 z[8], const float* __restrict__ Wb,
                                      const float* __restrict__ hb, int u)
{
#pragma unroll 1
    for (int jb = 0; jb < 48; jb += 4) {
        const float4 w0 = *(const float4*)(Wb + ((jb+0)*50 + u)*4);
        const float4 w1 = *(const float4*)(Wb + ((jb+1)*50 + u)*4);
        const float4 w2 = *(const float4*)(Wb + ((jb+2)*50 + u)*4);
        const float4 w3 = *(const float4*)(Wb + ((jb+3)*50 + u)*4);
#pragma unroll
        for (int r = 0; r < 8; r++) {
            const float4 hv = *(const float4*)(hb + r*HPAD + jb);
            fma4(z[r], w0, hv.x);
            fma4(z[r], w1, hv.y);
            fma4(z[r], w2, hv.z);
            fma4(z[r], w3, hv.w);
        }
    }
    // remainder j = 48, 49
    const float4 w48 = *(const float4*)(Wb + (48*50 + u)*4);
    const float4 w49 = *(const float4*)(Wb + (49*50 + u)*4);
#pragma unroll
    for (int r = 0; r < 8; r++) {
        const float h48 = hb[r*HPAD + 48];
        const float h49 = hb[r*HPAD + 49];
        fma4(z[r], w48, h48);
        fma4(z[r], w49, h49);
    }
}

__global__ void __launch_bounds__(NTHREADS, 1)
lstm_fused(const float* __restrict__ x,
           const float* __restrict__ Wih0, const float* __restrict__ Whh0,
           const float* __restrict__ bih0, const float* __restrict__ bhh0,
           const float* __restrict__ Wih1, const float* __restrict__ Whh1,
           const float* __restrict__ bih1, const float* __restrict__ bhh1,
           const float* __restrict__ Wih2, const float* __restrict__ Whh2,
           const float* __restrict__ bih2, const float* __restrict__ bhh2,
           const float* __restrict__ Wlin, const float* __restrict__ blin,
           float* __restrict__ out)
{
    extern __shared__ float sm[];
    float* W0 = sm + W0_OFF;
    float* W1 = sm + W1_OFF;
    float* W2 = sm + W2_OFF;
    float* HS = sm + HS_OFF;   // [3][BC][HPAD]
    float* XS = sm + XS_OFF;   // [BC][12]

    const int tid  = threadIdx.x;
    const int lane = tid & 31;
    const int wid  = tid >> 5;
    const int r0   = (wid >> 1) * 8;          // row group base
    const int u    = (wid & 1) * 32 + lane;   // unit id
    const bool act = (u < Hn);

    // ---- stage weights into shared with [k][u][gate] layout ----
    // layer0: k<12 -> Wih0 (input dim F), k in [12,62) -> Whh0
    for (int idx = tid; idx < 12400; idx += NTHREADS) {
        const int g  = idx & 3;
        const int uu = (idx >> 2) % 50;
        const int k  = idx / 200;
        W0[idx] = (k < 12) ? Wih0[(g*50 + uu)*12 + k]
                           : Whh0[(g*50 + uu)*50 + (k - 12)];
    }
    // layers 1,2: k<50 -> Wih (input = prev-layer h), k in [50,100) -> Whh
    for (int idx = tid; idx < 20000; idx += NTHREADS) {
        const int g  = idx & 3;
        const int uu = (idx >> 2) % 50;
        const int k  = idx / 200;
        W1[idx] = (k < 50) ? Wih1[(g*50 + uu)*50 + k]
                           : Whh1[(g*50 + uu)*50 + (k - 50)];
    }
    for (int idx = tid; idx < 20000; idx += NTHREADS) {
        const int g  = idx & 3;
        const int uu = (idx >> 2) % 50;
        const int k  = idx / 200;
        W2[idx] = (k < 50) ? Wih2[(g*50 + uu)*50 + k]
                           : Whh2[(g*50 + uu)*50 + (k - 50)];
    }
    for (int idx = tid; idx < 3*BC*HPAD; idx += NTHREADS) HS[idx] = 0.0f;

    float4 bias0 = make_float4(0.f,0.f,0.f,0.f);
    float4 bias1 = bias0, bias2 = bias0;
    if (act) {
        bias0 = make_float4(bih0[u]       + bhh0[u],
                            bih0[50 + u]  + bhh0[50 + u],
                            bih0[100 + u] + bhh0[100 + u],
                            bih0[150 + u] + bhh0[150 + u]);
        bias1 = make_float4(bih1[u]       + bhh1[u],
                            bih1[50 + u]  + bhh1[50 + u],
                            bih1[100 + u] + bhh1[100 + u],
                            bih1[150 + u] + bhh1[150 + u]);
        bias2 = make_float4(bih2[u]       + bhh2[u],
                            bih2[50 + u]  + bhh2[50 + u],
                            bih2[100 + u] + bhh2[100 + u],
                            bih2[150 + u] + bhh2[150 + u]);
    }

    float c0[8], c1[8], c2[8];
#pragma unroll
    for (int r = 0; r < 8; r++) { c0[r] = 0.f; c1[r] = 0.f; c2[r] = 0.f; }

    const long long bbase = (long long)blockIdx.x * BC;
    const float* xb = x + bbase * (Tn * Fn);

    __syncthreads();

    for (int t = 0; t < Tn; t++) {
        // ---- load x tile [BC][12] ----
        {
            int idx = tid;
            if (idx < BC*Fn) XS[idx] = xb[(idx/Fn)*(Tn*Fn) + t*Fn + (idx % Fn)];
            idx += NTHREADS;
            if (idx < BC*Fn) XS[idx] = xb[(idx/Fn)*(Tn*Fn) + t*Fn + (idx % Fn)];
        }
        __syncthreads();

        float hn[8];

        // ================= layer 0 =================
        if (act) {
            float4 z[8];
#pragma unroll
            for (int r = 0; r < 8; r++) z[r] = bias0;
#pragma unroll
            for (int k = 0; k < 12; k++) {
                const float4 w = *(const float4*)(W0 + (k*50 + u)*4);
#pragma unroll
                for (int r = 0; r < 8; r++) {
                    const float xv = XS[(r0 + r)*Fn + k];
                    fma4(z[r], w, xv);
                }
            }
            acc50(z, W0 + 12*200, HS + 0*(BC*HPAD) + r0*HPAD, u);
#pragma unroll
            for (int r = 0; r < 8; r++) {
                const float ig = sigmoidf_(z[r].x);
                const float fg = sigmoidf_(z[r].y);
                const float gg = tanhf(z[r].z);
                const float og = sigmoidf_(z[r].w);
                c0[r] = fg * c0[r] + ig * gg;
                hn[r] = og * tanhf(c0[r]);
            }
        }
        __syncthreads();
        if (act) {
#pragma unroll
            for (int r = 0; r < 8; r++) HS[0*(BC*HPAD) + (r0 + r)*HPAD + u] = hn[r];
        }
        __syncthreads();

        // ================= layer 1 =================
        if (act) {
            float4 z[8];
#pragma unroll
            for (int r = 0; r < 8; r++) z[r] = bias1;
            acc50(z, W1,          HS + 0*(BC*HPAD) + r0*HPAD, u);  // input = new h0
            acc50(z, W1 + 50*200, HS + 1*(BC*HPAD) + r0*HPAD, u);  // recurrent h1
#pragma unroll
            for (int r = 0; r < 8; r++) {
                const float ig = sigmoidf_(z[r].x);
                const float fg = sigmoidf_(z[r].y);
                const float gg = tanhf(z[r].z);
                const float og = sigmoidf_(z[r].w);
                c1[r] = fg * c1[r] + ig * gg;
                hn[r] = og * tanhf(c1[r]);
            }
        }
        __syncthreads();
        if (act) {
#pragma unroll
            for (int r = 0; r < 8; r++) HS[1*(BC*HPAD) + (r0 + r)*HPAD + u] = hn[r];
        }
        __syncthreads();

        // ================= layer 2 =================
        if (act) {
            float4 z[8];
#pragma unroll
            for (int r = 0; r < 8; r++) z[r] = bias2;
            acc50(z, W2,          HS + 1*(BC*HPAD) + r0*HPAD, u);  // input = new h1
            acc50(z, W2 + 50*200, HS + 2*(BC*HPAD) + r0*HPAD, u);  // recurrent h2
#pragma unroll
            for (int r = 0; r < 8; r++) {
                const float ig = sigmoidf_(z[r].x);
                const float fg = sigmoidf_(z[r].y);
                const float gg = tanhf(z[r].z);
                const float og = sigmoidf_(z[r].w);
                c2[r] = fg * c2[r] + ig * gg;
                hn[r] = og * tanhf(c2[r]);
            }
        }
        __syncthreads();
        if (act) {
#pragma unroll
            for (int r = 0; r < 8; r++) HS[2*(BC*HPAD) + (r0 + r)*HPAD + u] = hn[r];
        }
        __syncthreads();
    }

    // ---- final linear: out[b] = h2[b] . Wlin + blin ----
    if (tid < BC) {
        float s = blin[0];
#pragma unroll 10
        for (int uu = 0; uu < Hn; uu++)
            s += HS[2*(BC*HPAD) + tid*HPAD + uu] * Wlin[uu];
        out[bbase + tid] = s;
    }
}

extern "C" void kernel_launch(void* const* d_in, const int* in_sizes, int n_in,
                              void* d_out, int out_size)
{
    (void)in_sizes; (void)n_in; (void)out_size;
    const float* x    = (const float*)d_in[0];
    const float* Wih0 = (const float*)d_in[1];
    const float* Whh0 = (const float*)d_in[2];
    const float* bih0 = (const float*)d_in[3];
    const float* bhh0 = (const float*)d_in[4];
    const float* Wih1 = (const float*)d_in[5];
    const float* Whh1 = (const float*)d_in[6];
    const float* bih1 = (const float*)d_in[7];
    const float* bhh1 = (const float*)d_in[8];
    const float* Wih2 = (const float*)d_in[9];
    const float* Whh2 = (const float*)d_in[10];
    const float* bih2 = (const float*)d_in[11];
    const float* bhh2 = (const float*)d_in[12];
    const float* Wlin = (const float*)d_in[13];
    const float* blin = (const float*)d_in[14];
    float* out = (float*)d_out;

    cudaFuncSetAttribute(lstm_fused, cudaFuncAttributeMaxDynamicSharedMemorySize, SMEM_BYTES);
    lstm_fused<<<Bn / BC, NTHREADS, SMEM_BYTES>>>(
        x, Wih0, Whh0, bih0, bhh0,
        Wih1, Whh1, bih1, bhh1,
        Wih2, Whh2, bih2, bhh2,
        Wlin, blin, out);
}

// round 4
// speedup vs baseline: 1.0115x; 1.0115x over previous
#include <cuda_runtime.h>

// Problem constants
#define Tn 336
#define Fn 12
#define Hn 50
#define Bn 4096
#define BC 32          // batch rows per CTA
#define NTHREADS 512
#define HPAD 52        // h row stride (float4-aligned)
#define RPG 4          // rows per group (8 groups x 2 warps)

// shared memory float offsets
#define W0_OFF 0                 // layer0 combined [62][50][4]  = 12400 floats
#define W1_OFF 12400             // layer1 combined [100][50][4] = 20000
#define W2_OFF 32400             // layer2 combined [100][50][4] = 20000
#define HS_OFF 52400             // h state  3 * 32 * 52 = 4992
#define XS_OFF 57392             // x tile   32 * 12 = 384
#define SMEM_FLOATS 57776
#define SMEM_BYTES (SMEM_FLOATS * 4)

__device__ __forceinline__ void fma4(float4& z, const float4 wv, const float s) {
    z.x += wv.x * s;
    z.y += wv.y * s;
    z.z += wv.z * s;
    z.w += wv.w * s;
}

__device__ __forceinline__ float sigmoidf_(float v) {
    return 1.0f / (1.0f + __expf(-v));
}

// precise-enough tanh: 1 - 2/(1+e^{2x});  ~1e-7 rel err, 2 MUFU + few FMA
__device__ __forceinline__ float tanhf_(float v) {
    const float e = __expf(2.0f * v);
    return 1.0f - 2.0f / (e + 1.0f);
}

// named barrier for a 2-warp group (ids 1..8; 0 reserved for __syncthreads)
__device__ __forceinline__ void barg(int id) {
    asm volatile("bar.sync %0, 64;" :: "r"(id) : "memory");
}

// Accumulate z[r] += sum_{j<50} W[j][u][gate] * h[r][j]   (RPG rows)
__device__ __forceinline__ void acc50(float4 z[RPG], const float* __restrict__ Wb,
                                      const float* __restrict__ hb, int u)
{
#pragma unroll 1
    for (int jb = 0; jb < 48; jb += 4) {
        const float4 w0 = *(const float4*)(Wb + ((jb+0)*50 + u)*4);
        const float4 w1 = *(const float4*)(Wb + ((jb+1)*50 + u)*4);
        const float4 w2 = *(const float4*)(Wb + ((jb+2)*50 + u)*4);
        const float4 w3 = *(const float4*)(Wb + ((jb+3)*50 + u)*4);
#pragma unroll
        for (int r = 0; r < RPG; r++) {
            const float4 hv = *(const float4*)(hb + r*HPAD + jb);
            fma4(z[r], w0, hv.x);
            fma4(z[r], w1, hv.y);
            fma4(z[r], w2, hv.z);
            fma4(z[r], w3, hv.w);
        }
    }
    const float4 w48 = *(const float4*)(Wb + (48*50 + u)*4);
    const float4 w49 = *(const float4*)(Wb + (49*50 + u)*4);
#pragma unroll
    for (int r = 0; r < RPG; r++) {
        const float h48 = hb[r*HPAD + 48];
        const float h49 = hb[r*HPAD + 49];
        fma4(z[r], w48, h48);
        fma4(z[r], w49, h49);
    }
}

__global__ void __launch_bounds__(NTHREADS, 1)
lstm_fused(const float* __restrict__ x,
           const float* __restrict__ Wih0, const float* __restrict__ Whh0,
           const float* __restrict__ bih0, const float* __restrict__ bhh0,
           const float* __restrict__ Wih1, const float* __restrict__ Whh1,
           const float* __restrict__ bih1, const float* __restrict__ bhh1,
           const float* __restrict__ Wih2, const float* __restrict__ Whh2,
           const float* __restrict__ bih2, const float* __restrict__ bhh2,
           const float* __restrict__ Wlin, const float* __restrict__ blin,
           float* __restrict__ out)
{
    extern __shared__ float sm[];
    float* W0 = sm + W0_OFF;
    float* W1 = sm + W1_OFF;
    float* W2 = sm + W2_OFF;
    float* HS = sm + HS_OFF;   // [3][BC][HPAD]
    float* XS = sm + XS_OFF;   // [BC][12]

    const int tid   = threadIdx.x;
    const int lane  = tid & 31;
    const int wid   = tid >> 5;
    const int grp   = wid >> 1;               // 0..7
    const int bid   = grp + 1;                // named barrier id
    const int r0    = grp * RPG;              // row base (4 rows)
    const int u     = (wid & 1) * 32 + lane;  // unit id
    const bool act  = (u < Hn);
    const int gtid  = tid & 63;               // thread id within group

    // ---- stage weights into shared with [k][u][gate] layout ----
    for (int idx = tid; idx < 12400; idx += NTHREADS) {
        const int g  = idx & 3;
        const int uu = (idx >> 2) % 50;
        const int k  = idx / 200;
        W0[idx] = (k < 12) ? Wih0[(g*50 + uu)*12 + k]
                           : Whh0[(g*50 + uu)*50 + (k - 12)];
    }
    for (int idx = tid; idx < 20000; idx += NTHREADS) {
        const int g  = idx & 3;
        const int uu = (idx >> 2) % 50;
        const int k  = idx / 200;
        W1[idx] = (k < 50) ? Wih1[(g*50 + uu)*50 + k]
                           : Whh1[(g*50 + uu)*50 + (k - 50)];
    }
    for (int idx = tid; idx < 20000; idx += NTHREADS) {
        const int g  = idx & 3;
        const int uu = (idx >> 2) % 50;
        const int k  = idx / 200;
        W2[idx] = (k < 50) ? Wih2[(g*50 + uu)*50 + k]
                           : Whh2[(g*50 + uu)*50 + (k - 50)];
    }
    for (int idx = tid; idx < 3*BC*HPAD; idx += NTHREADS) HS[idx] = 0.0f;

    float4 bias0 = make_float4(0.f,0.f,0.f,0.f);
    float4 bias1 = bias0, bias2 = bias0;
    if (act) {
        bias0 = make_float4(bih0[u]       + bhh0[u],
                            bih0[50 + u]  + bhh0[50 + u],
                            bih0[100 + u] + bhh0[100 + u],
                            bih0[150 + u] + bhh0[150 + u]);
        bias1 = make_float4(bih1[u]       + bhh1[u],
                            bih1[50 + u]  + bhh1[50 + u],
                            bih1[100 + u] + bhh1[100 + u],
                            bih1[150 + u] + bhh1[150 + u]);
        bias2 = make_float4(bih2[u]       + bhh2[u],
                            bih2[50 + u]  + bhh2[50 + u],
                            bih2[100 + u] + bhh2[100 + u],
                            bih2[150 + u] + bhh2[150 + u]);
    }

    float c0[RPG], c1[RPG], c2[RPG];
#pragma unroll
    for (int r = 0; r < RPG; r++) { c0[r] = 0.f; c1[r] = 0.f; c2[r] = 0.f; }

    const long long bbase = (long long)blockIdx.x * BC;
    const float* xb = x + bbase * (Tn * Fn);

    // x-load index for this thread (group loads its own 4 rows, 48 floats)
    const int xrow = r0 + gtid / Fn;          // valid if gtid < 48
    const int xcol = gtid % Fn;

    __syncthreads();

    float* HS0 = HS + 0*(BC*HPAD) + r0*HPAD;
    float* HS1 = HS + 1*(BC*HPAD) + r0*HPAD;
    float* HS2 = HS + 2*(BC*HPAD) + r0*HPAD;
    float* XSg = XS + r0*Fn;

    for (int t = 0; t < Tn; t++) {
        // ---- group-local x tile load: 4 rows x 12 ----
        if (gtid < RPG*Fn)
            XSg[gtid] = xb[xrow*(Tn*Fn) + t*Fn + xcol];
        barg(bid);

        float hn[RPG];

        // ================= layer 0 =================
        if (act) {
            float4 z[RPG];
#pragma unroll
            for (int r = 0; r < RPG; r++) z[r] = bias0;
#pragma unroll
            for (int k = 0; k < 12; k++) {
                const float4 w = *(const float4*)(W0 + (k*50 + u)*4);
#pragma unroll
                for (int r = 0; r < RPG; r++)
                    fma4(z[r], w, XSg[r*Fn + k]);
            }
            acc50(z, W0 + 12*200, HS0, u);
#pragma unroll
            for (int r = 0; r < RPG; r++) {
                const float ig = sigmoidf_(z[r].x);
                const float fg = sigmoidf_(z[r].y);
                const float gg = tanhf_(z[r].z);
                const float og = sigmoidf_(z[r].w);
                c0[r] = fg * c0[r] + ig * gg;
                hn[r] = og * tanhf_(c0[r]);
            }
        }
        barg(bid);
        if (act) {
#pragma unroll
            for (int r = 0; r < RPG; r++) HS0[r*HPAD + u] = hn[r];
        }
        barg(bid);

        // ================= layer 1 =================
        if (act) {
            float4 z[RPG];
#pragma unroll
            for (int r = 0; r < RPG; r++) z[r] = bias1;
            acc50(z, W1,          HS0, u);
            acc50(z, W1 + 50*200, HS1, u);
#pragma unroll
            for (int r = 0; r < RPG; r++) {
                const float ig = sigmoidf_(z[r].x);
                const float fg = sigmoidf_(z[r].y);
                const float gg = tanhf_(z[r].z);
                const float og = sigmoidf_(z[r].w);
                c1[r] = fg * c1[r] + ig * gg;
                hn[r] = og * tanhf_(c1[r]);
            }
        }
        barg(bid);
        if (act) {
#pragma unroll
            for (int r = 0; r < RPG; r++) HS1[r*HPAD + u] = hn[r];
        }
        barg(bid);

        // ================= layer 2 =================
        if (act) {
            float4 z[RPG];
#pragma unroll
            for (int r = 0; r < RPG; r++) z[r] = bias2;
            acc50(z, W2,          HS1, u);
            acc50(z, W2 + 50*200, HS2, u);
#pragma unroll
            for (int r = 0; r < RPG; r++) {
                const float ig = sigmoidf_(z[r].x);
                const float fg = sigmoidf_(z[r].y);
                const float gg = tanhf_(z[r].z);
                const float og = sigmoidf_(z[r].w);
                c2[r] = fg * c2[r] + ig * gg;
                hn[r] = og * tanhf_(c2[r]);
            }
        }
        barg(bid);
        if (act) {
#pragma unroll
            for (int r = 0; r < RPG; r++) HS2[r*HPAD + u] = hn[r];
        }
        barg(bid);
    }

    __syncthreads();

    // ---- final linear: out[b] = h2[b] . Wlin + blin ----
    if (tid < BC) {
        float s = blin[0];
#pragma unroll 10
        for (int uu = 0; uu < Hn; uu++)
            s += HS[2*(BC*HPAD) + tid*HPAD + uu] * Wlin[uu];
        out[bbase + tid] = s;
    }
}

extern "C" void kernel_launch(void* const* d_in, const int* in_sizes, int n_in,
                              void* d_out, int out_size)
{
    (void)in_sizes; (void)n_in; (void)out_size;
    const float* x    = (const float*)d_in[0];
    const float* Wih0 = (const float*)d_in[1];
    const float* Whh0 = (const float*)d_in[2];
    const float* bih0 = (const float*)d_in[3];
    const float* bhh0 = (const float*)d_in[4];
    const float* Wih1 = (const float*)d_in[5];
    const float* Whh1 = (const float*)d_in[6];
    const float* bih1 = (const float*)d_in[7];
    const float* bhh1 = (const float*)d_in[8];
    const float* Wih2 = (const float*)d_in[9];
    const float* Whh2 = (const float*)d_in[10];
    const float* bih2 = (const float*)d_in[11];
    const float* bhh2 = (const float*)d_in[12];
    const float* Wlin = (const float*)d_in[13];
    const float* blin = (const float*)d_in[14];
    float* out = (float*)d_out;

    cudaFuncSetAttribute(lstm_fused, cudaFuncAttributeMaxDynamicSharedMemorySize, SMEM_BYTES);
    lstm_fused<<<Bn / BC, NTHREADS, SMEM_BYTES>>>(
        x, Wih0, Whh0, bih0, bhh0,
        Wih1, Whh1, bih1, bhh1,
        Wih2, Whh2, bih2, bhh2,
        Wlin, blin, out);
}

// round 5
// speedup vs baseline: 1.1298x; 1.1170x over previous
#include <cuda_runtime.h>

// Problem constants
#define Tn 336
#define Fn 12
#define Hn 50
#define Bn 4096
#define BC 32          // batch rows per CTA
#define NTHREADS 512
#define HPAD 52        // h row stride (float4-aligned)
#define RPG 4          // rows per group (8 groups x 2 warps)

// shared memory float offsets
#define W0_OFF 0                 // layer0 combined [62][50][4]  = 12400 floats
#define W1_OFF 12400             // layer1 combined [100][50][4] = 20000
#define W2_OFF 32400             // layer2 combined [100][50][4] = 20000
#define HS_OFF 52400             // h state  3 * 32 * 52 = 4992
#define XS_OFF 57392             // x tile   32 * 12 = 384
#define SMEM_FLOATS 57776
#define SMEM_BYTES (SMEM_FLOATS * 4)

typedef unsigned long long u64;

// packed dual-fp32 FMA (sm_103a FFMA2): z += w * h (elementwise on 2 lanes)
__device__ __forceinline__ void ffma2(u64& z, const u64 w, const u64 h) {
    asm("fma.rn.f32x2 %0, %1, %2, %0;" : "+l"(z) : "l"(w), "l"(h));
}
// broadcast a scalar into both halves of a b64
__device__ __forceinline__ u64 dup2(const float s) {
    u64 r; asm("mov.b64 %0, {%1, %1};" : "=l"(r) : "f"(s)); return r;
}
__device__ __forceinline__ u64 pack2(const float lo, const float hi) {
    u64 r; asm("mov.b64 %0, {%1, %2};" : "=l"(r) : "f"(lo), "f"(hi)); return r;
}
__device__ __forceinline__ void unpack2(const u64 v, float& lo, float& hi) {
    asm("mov.b64 {%0, %1}, %2;" : "=f"(lo), "=f"(hi) : "l"(v));
}

__device__ __forceinline__ float sigmoidf_(float v) {
    return 1.0f / (1.0f + __expf(-v));
}
// precise-enough tanh: 1 - 2/(1+e^{2x}); ~1e-7 rel err
__device__ __forceinline__ float tanhf_(float v) {
    const float e = __expf(2.0f * v);
    return 1.0f - 2.0f / (e + 1.0f);
}

// named barrier for a 2-warp group (ids 1..8; 0 reserved for __syncthreads)
__device__ __forceinline__ void barg(int id) {
    asm volatile("bar.sync %0, 64;" :: "r"(id) : "memory");
}

struct Z2 { u64 a, b; };   // a = gates (i,f), b = gates (g,o)

// z[r] += sum_{j<50} W[j][u][:] * h[r][j], packed FFMA2 form.
// Wb layout: (j,u,g) at Wb[(j*50+u)*4+g]; each (j,u) row = 16B = 2 b64 gate-pairs.
__device__ __forceinline__ void acc50(Z2 z[RPG], const float* __restrict__ Wb,
                                      const float* __restrict__ hb, int u)
{
#pragma unroll 1
    for (int jb = 0; jb < 48; jb += 4) {
        const ulonglong2 w0 = *(const ulonglong2*)(Wb + ((jb+0)*50 + u)*4);
        const ulonglong2 w1 = *(const ulonglong2*)(Wb + ((jb+1)*50 + u)*4);
        const ulonglong2 w2 = *(const ulonglong2*)(Wb + ((jb+2)*50 + u)*4);
        const ulonglong2 w3 = *(const ulonglong2*)(Wb + ((jb+3)*50 + u)*4);
#pragma unroll
        for (int r = 0; r < RPG; r++) {
            const float4 hv = *(const float4*)(hb + r*HPAD + jb);
            const u64 h0 = dup2(hv.x);
            const u64 h1 = dup2(hv.y);
            const u64 h2 = dup2(hv.z);
            const u64 h3 = dup2(hv.w);
            ffma2(z[r].a, w0.x, h0); ffma2(z[r].b, w0.y, h0);
            ffma2(z[r].a, w1.x, h1); ffma2(z[r].b, w1.y, h1);
            ffma2(z[r].a, w2.x, h2); ffma2(z[r].b, w2.y, h2);
            ffma2(z[r].a, w3.x, h3); ffma2(z[r].b, w3.y, h3);
        }
    }
    const ulonglong2 w48 = *(const ulonglong2*)(Wb + (48*50 + u)*4);
    const ulonglong2 w49 = *(const ulonglong2*)(Wb + (49*50 + u)*4);
#pragma unroll
    for (int r = 0; r < RPG; r++) {
        const u64 h48 = dup2(hb[r*HPAD + 48]);
        const u64 h49 = dup2(hb[r*HPAD + 49]);
        ffma2(z[r].a, w48.x, h48); ffma2(z[r].b, w48.y, h48);
        ffma2(z[r].a, w49.x, h49); ffma2(z[r].b, w49.y, h49);
    }
}

__global__ void __launch_bounds__(NTHREADS, 1)
lstm_fused(const float* __restrict__ x,
           const float* __restrict__ Wih0, const float* __restrict__ Whh0,
           const float* __restrict__ bih0, const float* __restrict__ bhh0,
           const float* __restrict__ Wih1, const float* __restrict__ Whh1,
           const float* __restrict__ bih1, const float* __restrict__ bhh1,
           const float* __restrict__ Wih2, const float* __restrict__ Whh2,
           const float* __restrict__ bih2, const float* __restrict__ bhh2,
           const float* __restrict__ Wlin, const float* __restrict__ blin,
           float* __restrict__ out)
{
    extern __shared__ float sm[];
    float* W0 = sm + W0_OFF;
    float* W1 = sm + W1_OFF;
    float* W2 = sm + W2_OFF;
    float* HS = sm + HS_OFF;   // [3][BC][HPAD]
    float* XS = sm + XS_OFF;   // [BC][12]

    const int tid   = threadIdx.x;
    const int lane  = tid & 31;
    const int wid   = tid >> 5;
    const int grp   = wid >> 1;               // 0..7
    const int bid   = grp + 1;                // named barrier id
    const int r0    = grp * RPG;              // row base (4 rows)
    const int u     = (wid & 1) * 32 + lane;  // unit id
    const bool act  = (u < Hn);
    const int gtid  = tid & 63;               // thread id within group

    // ---- stage weights into shared with [k][u][gate] layout ----
    for (int idx = tid; idx < 12400; idx += NTHREADS) {
        const int g  = idx & 3;
        const int uu = (idx >> 2) % 50;
        const int k  = idx / 200;
        W0[idx] = (k < 12) ? Wih0[(g*50 + uu)*12 + k]
                           : Whh0[(g*50 + uu)*50 + (k - 12)];
    }
    for (int idx = tid; idx < 20000; idx += NTHREADS) {
        const int g  = idx & 3;
        const int uu = (idx >> 2) % 50;
        const int k  = idx / 200;
        W1[idx] = (k < 50) ? Wih1[(g*50 + uu)*50 + k]
                           : Whh1[(g*50 + uu)*50 + (k - 50)];
    }
    for (int idx = tid; idx < 20000; idx += NTHREADS) {
        const int g  = idx & 3;
        const int uu = (idx >> 2) % 50;
        const int k  = idx / 200;
        W2[idx] = (k < 50) ? Wih2[(g*50 + uu)*50 + k]
                           : Whh2[(g*50 + uu)*50 + (k - 50)];
    }
    for (int idx = tid; idx < 3*BC*HPAD; idx += NTHREADS) HS[idx] = 0.0f;

    u64 b0a = 0, b0b = 0, b1a = 0, b1b = 0, b2a = 0, b2b = 0;
    if (act) {
        b0a = pack2(bih0[u]       + bhh0[u],       bih0[50 + u]  + bhh0[50 + u]);
        b0b = pack2(bih0[100 + u] + bhh0[100 + u], bih0[150 + u] + bhh0[150 + u]);
        b1a = pack2(bih1[u]       + bhh1[u],       bih1[50 + u]  + bhh1[50 + u]);
        b1b = pack2(bih1[100 + u] + bhh1[100 + u], bih1[150 + u] + bhh1[150 + u]);
        b2a = pack2(bih2[u]       + bhh2[u],       bih2[50 + u]  + bhh2[50 + u]);
        b2b = pack2(bih2[100 + u] + bhh2[100 + u], bih2[150 + u] + bhh2[150 + u]);
    }

    float c0[RPG], c1[RPG], c2[RPG];
#pragma unroll
    for (int r = 0; r < RPG; r++) { c0[r] = 0.f; c1[r] = 0.f; c2[r] = 0.f; }

    const long long bbase = (long long)blockIdx.x * BC;
    const float* xb = x + bbase * (Tn * Fn);

    const int xrow = r0 + gtid / Fn;          // valid if gtid < 48
    const int xcol = gtid % Fn;

    __syncthreads();

    float* HS0 = HS + 0*(BC*HPAD) + r0*HPAD;
    float* HS1 = HS + 1*(BC*HPAD) + r0*HPAD;
    float* HS2 = HS + 2*(BC*HPAD) + r0*HPAD;
    float* XSg = XS + r0*Fn;

    for (int t = 0; t < Tn; t++) {
        // ---- group-local x tile load: 4 rows x 12 ----
        if (gtid < RPG*Fn)
            XSg[gtid] = xb[xrow*(Tn*Fn) + t*Fn + xcol];
        barg(bid);

        float hn[RPG];

        // ================= layer 0 =================
        if (act) {
            Z2 z[RPG];
#pragma unroll
            for (int r = 0; r < RPG; r++) { z[r].a = b0a; z[r].b = b0b; }
#pragma unroll
            for (int k = 0; k < 12; k++) {
                const ulonglong2 w = *(const ulonglong2*)(W0 + (k*50 + u)*4);
#pragma unroll
                for (int r = 0; r < RPG; r++) {
                    const u64 xv = dup2(XSg[r*Fn + k]);
                    ffma2(z[r].a, w.x, xv);
                    ffma2(z[r].b, w.y, xv);
                }
            }
            acc50(z, W0 + 12*200, HS0, u);
#pragma unroll
            for (int r = 0; r < RPG; r++) {
                float zi, zf, zg, zo;
                unpack2(z[r].a, zi, zf);
                unpack2(z[r].b, zg, zo);
                const float ig = sigmoidf_(zi);
                const float fg = sigmoidf_(zf);
                const float gg = tanhf_(zg);
                const float og = sigmoidf_(zo);
                c0[r] = fg * c0[r] + ig * gg;
                hn[r] = og * tanhf_(c0[r]);
            }
        }
        barg(bid);
        if (act) {
#pragma unroll
            for (int r = 0; r < RPG; r++) HS0[r*HPAD + u] = hn[r];
        }
        barg(bid);

        // ================= layer 1 =================
        if (act) {
            Z2 z[RPG];
#pragma unroll
            for (int r = 0; r < RPG; r++) { z[r].a = b1a; z[r].b = b1b; }
            acc50(z, W1,          HS0, u);
            acc50(z, W1 + 50*200, HS1, u);
#pragma unroll
            for (int r = 0; r < RPG; r++) {
                float zi, zf, zg, zo;
                unpack2(z[r].a, zi, zf);
                unpack2(z[r].b, zg, zo);
                const float ig = sigmoidf_(zi);
                const float fg = sigmoidf_(zf);
                const float gg = tanhf_(zg);
                const float og = sigmoidf_(zo);
                c1[r] = fg * c1[r] + ig * gg;
                hn[r] = og * tanhf_(c1[r]);
            }
        }
        barg(bid);
        if (act) {
#pragma unroll
            for (int r = 0; r < RPG; r++) HS1[r*HPAD + u] = hn[r];
        }
        barg(bid);

        // ================= layer 2 =================
        if (act) {
            Z2 z[RPG];
#pragma unroll
            for (int r = 0; r < RPG; r++) { z[r].a = b2a; z[r].b = b2b; }
            acc50(z, W2,          HS1, u);
            acc50(z, W2 + 50*200, HS2, u);
#pragma unroll
            for (int r = 0; r < RPG; r++) {
                float zi, zf, zg, zo;
                unpack2(z[r].a, zi, zf);
                unpack2(z[r].b, zg, zo);
                const float ig = sigmoidf_(zi);
                const float fg = sigmoidf_(zf);
                const float gg = tanhf_(zg);
                const float og = sigmoidf_(zo);
                c2[r] = fg * c2[r] + ig * gg;
                hn[r] = og * tanhf_(c2[r]);
            }
        }
        barg(bid);
        if (act) {
#pragma unroll
            for (int r = 0; r < RPG; r++) HS2[r*HPAD + u] = hn[r];
        }
        barg(bid);
    }

    __syncthreads();

    // ---- final linear: out[b] = h2[b] . Wlin + blin ----
    if (tid < BC) {
        float s = blin[0];
#pragma unroll 10
        for (int uu = 0; uu < Hn; uu++)
            s += HS[2*(BC*HPAD) + tid*HPAD + uu] * Wlin[uu];
        out[bbase + tid] = s;
    }
}

extern "C" void kernel_launch(void* const* d_in, const int* in_sizes, int n_in,
                              void* d_out, int out_size)
{
    (void)in_sizes; (void)n_in; (void)out_size;
    const float* x    = (const float*)d_in[0];
    const float* Wih0 = (const float*)d_in[1];
    const float* Whh0 = (const float*)d_in[2];
    const float* bih0 = (const float*)d_in[3];
    const float* bhh0 = (const float*)d_in[4];
    const float* Wih1 = (const float*)d_in[5];
    const float* Whh1 = (const float*)d_in[6];
    const float* bih1 = (const float*)d_in[7];
    const float* bhh1 = (const float*)d_in[8];
    const float* Wih2 = (const float*)d_in[9];
    const float* Whh2 = (const float*)d_in[10];
    const float* bih2 = (const float*)d_in[11];
    const float* bhh2 = (const float*)d_in[12];
    const float* Wlin = (const float*)d_in[13];
    const float* blin = (const float*)d_in[14];
    float* out = (float*)d_out;

    cudaFuncSetAttribute(lstm_fused, cudaFuncAttributeMaxDynamicSharedMemorySize, SMEM_BYTES);
    lstm_fused<<<Bn / BC, NTHREADS, SMEM_BYTES>>>(
        x, Wih0, Whh0, bih0, bhh0,
        Wih1, Whh1, bih1, bhh1,
        Wih2, Whh2, bih2, bhh2,
        Wlin, blin, out);
}